// round 13
// baseline (speedup 1.0000x reference)
#include <cuda_runtime.h>

// Single fused ball-query kernel, direct-binned 12^3 grid, ONE grid barrier.
// N1=4096 queries, N2=16384 refs, K=32, r=0.08, points uniform [0,1)^3.
//
// R13 = R12 with the OOB fix: dead rows (zz/yy outside grid or pruned) had
// negative c0 -> negative rbase -> unconditional load crashed. rbase is now
// clamped to 0 for dead rows; their lanes load cell 0 harmlessly (always
// in-bounds, L1-hot) and are excluded from the hit ballot by lane < tt (=0).
// Upper end covered by +128-slot g_cp padding.
//
// R12 design (unchanged): ballot-append (no shared atomics, branch-free
// bodies), unconditional candidate loads, shfl rank epilogue (cc<=64, with
// LDS fallback), staged coalesced output, single fence-free barrier,
// generation-parity double-buffered counters.
//
// Replay-safe: g_tick monotone; parity zeroing re-establishes the counter
// invariant each call. Deterministic: hits ranked by unique original index.
//
// Hit predicate bit-identical to verified formula (rel_err 0.0 x11):
//   s = ((x*x + y*y) + z*z)  (mul/add, no fma contraction)
//   dot = fmaf(z1,z2, fmaf(y1,y2, x1*x2))
//   d2  = (s1 + s2) - 2*dot;  hit iff d2 <= r^2

#define BQ_N1 4096
#define BQ_N2 16384
#define BQ_K 32
#define BQ_R2 0.0064f
#define BQ_R2P 0.00641f
#define BQ_G 12
#define BQ_NC (BQ_G * BQ_G * BQ_G)  // 1728
#define BQ_CAP 48
#define BQ_BUF 128
#define NBLK 256
#define NTHR 512
#define NWARP 16
#define ZPB 7                       // 256*7 = 1792 >= 1728
#define PPB 64                      // 256*64 = 16384
#define FULLW 0xffffffffu

__device__ unsigned g_tick;             // entry tickets (monotone)
__device__ unsigned g_arrive;           // barrier arrival tickets (monotone)
__device__ unsigned g_release;          // barrier release generations
__device__ int g_n[2][BQ_NC];           // parity-double-buffered counts
__device__ float4 g_cp[BQ_NC * BQ_CAP + 128];  // padded: OOB lane addrs safe

__device__ __forceinline__ int cell1(float v) {
    int c = (int)(v * (float)BQ_G);
    return c < 0 ? 0 : (c > BQ_G - 1 ? BQ_G - 1 : c);
}

// Fence-free grid barrier (acq_rel ticket / release-word split).
// 256 blocks co-resident (launch_bounds(512,2): 296 >= 256) -> deadlock-free.
__device__ __forceinline__ void gbar() {
    __syncthreads();
    if (threadIdx.x == 0) {
        unsigned my;
        asm volatile("atom.add.acq_rel.gpu.global.u32 %0, [%1], %2;"
                     : "=r"(my) : "l"(&g_arrive), "r"(1u) : "memory");
        unsigned target = my / NBLK + 1u;
        if (my % NBLK == NBLK - 1u) {
            asm volatile("red.add.release.gpu.global.u32 [%0], %1;"
                         :: "l"(&g_release), "r"(1u) : "memory");
        } else {
            unsigned v;
            do {
                __nanosleep(20);
                asm volatile("ld.acquire.gpu.global.u32 %0, [%1];"
                             : "=r"(v) : "l"(&g_release) : "memory");
            } while (v < target);
        }
    }
    __syncthreads();
}

__global__ __launch_bounds__(NTHR, 2) void bq_all(const float* __restrict__ p1,
                                                  const float* __restrict__ p2,
                                                  float* __restrict__ out) {
    __shared__ int sh_key[NWARP][BQ_BUF];     // 8 KB packed hit records
    __shared__ float sh_out[NWARP][BQ_K * 4]; // 8 KB staged outputs
    __shared__ unsigned s_call;

    int tid = threadIdx.x;
    int warp = tid >> 5;
    int lane = tid & 31;
    int q = blockIdx.x * NWARP + warp;        // 4096 queries, one per warp
    unsigned below = (1u << lane) - 1u;

    // ---- Entry: non-blocking call-index ticket ----
    if (tid == 0) s_call = atomicAdd(&g_tick, 1u) / NBLK;
    __syncthreads();
    int par = (int)(s_call & 1u);
    int* cnts = g_n[par];

    // Zero the OTHER parity buffer for the next call (no reader exists).
    if (tid < ZPB) {
        int c = blockIdx.x * ZPB + tid;
        if (c < BQ_NC) g_n[1 - par][c] = 0;
    }

    // ---- Build: 64 points/block into g_n[par]/g_cp ----
    if (tid < PPB) {
        int j = blockIdx.x * PPB + tid;
        float px = p2[3 * j + 0];
        float py = p2[3 * j + 1];
        float pz = p2[3 * j + 2];
        int c = (cell1(pz) * BQ_G + cell1(py)) * BQ_G + cell1(px);
        int slot = atomicAdd(&cnts[c], 1);
        if (slot < BQ_CAP)
            g_cp[c * BQ_CAP + slot] =
                make_float4(px, py, pz, __int_as_float(j));
    }

    // Query-point setup (overlaps build latency).
    float x1 = p1[3 * q + 0];
    float y1 = p1[3 * q + 1];
    float z1 = p1[3 * q + 2];
    float s1 = __fadd_rn(__fadd_rn(__fmul_rn(x1, x1), __fmul_rn(y1, y1)),
                         __fmul_rn(z1, z1));
    int cx = cell1(x1), cy = cell1(y1), cz = cell1(z1);
    int xlo = cx > 0 ? cx - 1 : 0;
    int xhi = cx < BQ_G - 1 ? cx + 1 : BQ_G - 1;
    const float invG = 1.0f / (float)BQ_G;
    float dxl = x1 - (float)cx * invG, dxr = (float)(cx + 1) * invG - x1;
    float dyl = y1 - (float)cy * invG, dyr = (float)(cy + 1) * invG - y1;
    float dzl = z1 - (float)cz * invG, dzr = (float)(cz + 1) * invG - z1;
    float dxl2 = dxl * dxl, dxr2 = dxr * dxr;

    gbar();  // build complete -> query may read

    // ---- Query ----
    int* keyb = sh_key[warp];

    // Row descriptors: all 27 counter loads issue as one independent wave.
    int rbase[9], rpack[9];  // rpack = n0 | n01<<8 | tot<<16
    #pragma unroll
    for (int r = 0; r < 9; r++) {
        int dzi = r / 3 - 1, dyi = r % 3 - 1;
        int zz = cz + dzi, yy = cy + dyi;
        float ddz = (dzi < 0) ? dzl : ((dzi > 0) ? dzr : 0.0f);
        float ddy = (dyi < 0) ? dyl : ((dyi > 0) ? dyr : 0.0f);
        float dyz2 = ddz * ddz + ddy * ddy;
        bool ok = (zz >= 0) && (zz < BQ_G) && (yy >= 0) && (yy < BQ_G) &&
                  (dyz2 <= BQ_R2P);
        int xl = xlo, xh = xhi;
        if (xl < cx && dxl2 + dyz2 > BQ_R2P) xl = cx;
        if (xh > cx && dxr2 + dyz2 > BQ_R2P) xh = cx;
        int c0 = (zz * BQ_G + yy) * BQ_G + xl;
        int nc = xh - xl + 1;
        int n0 = 0, n1 = 0, n2 = 0;
        if (ok) {
            n0 = min(cnts[c0], BQ_CAP);
            if (nc > 1) n1 = min(cnts[c0 + 1], BQ_CAP);
            if (nc > 2) n2 = min(cnts[c0 + 2], BQ_CAP);
        }
        // Dead rows get rbase=0 so the unconditional load below is always
        // in-bounds (their lanes are excluded by lane < tt anyway).
        rbase[r] = ok ? c0 * BQ_CAP : 0;
        rpack[r] = n0 | ((n0 + n1) << 8) | ((n0 + n1 + n2) << 16);
    }

    int cnt = 0;  // warp-uniform hit count (ballot-maintained)

    // Rows in 3 groups of 3: each group's candidate loads issue back-to-back;
    // batch bodies are branch-free (ballot executed by all lanes).
    #pragma unroll
    for (int grp = 0; grp < 3; grp++) {
        float4 pb[3];
        int ta[3], tt[3];
        #pragma unroll
        for (int k = 0; k < 3; k++) {
            int r = grp * 3 + k;
            int n0 = rpack[r] & 0xff;
            int n01 = (rpack[r] >> 8) & 0xff;
            tt[k] = rpack[r] >> 16;
            int t = lane;
            int a = rbase[r] + (t < n0 ? t
                    : (t < n01 ? BQ_CAP + t - n0 : 2 * BQ_CAP + t - n01));
            ta[k] = a;
            pb[k] = g_cp[a];  // unconditional; rbase clamp + padding keep a valid
        }
        #pragma unroll
        for (int k = 0; k < 3; k++) {
            int r = grp * 3 + k;
            {
                float4 p = pb[k];
                float s2 = __fadd_rn(
                    __fadd_rn(__fmul_rn(p.x, p.x), __fmul_rn(p.y, p.y)),
                    __fmul_rn(p.z, p.z));
                float dot = fmaf(z1, p.z, fmaf(y1, p.y, __fmul_rn(x1, p.x)));
                float d2 = __fsub_rn(__fadd_rn(s1, s2), __fmul_rn(2.0f, dot));
                bool hit = (lane < tt[k]) && (d2 <= BQ_R2);
                unsigned m = __ballot_sync(FULLW, hit);
                int pos = cnt + __popc(m & below);
                if (hit && pos < BQ_BUF)
                    keyb[pos] = (__float_as_int(p.w) << 17) | ta[k];
                cnt += __popc(m);
            }
            // Overflow batches: warp-uniform trip count (tt[k] uniform).
            int n0 = rpack[r] & 0xff;
            int n01 = (rpack[r] >> 8) & 0xff;
            for (int b = 32; b < tt[k]; b += 32) {
                int t = b + lane;
                int a = rbase[r] + (t < n0 ? t
                        : (t < n01 ? BQ_CAP + t - n0 : 2 * BQ_CAP + t - n01));
                float4 p = g_cp[a];
                float s2 = __fadd_rn(
                    __fadd_rn(__fmul_rn(p.x, p.x), __fmul_rn(p.y, p.y)),
                    __fmul_rn(p.z, p.z));
                float dot = fmaf(z1, p.z, fmaf(y1, p.y, __fmul_rn(x1, p.x)));
                float d2 = __fsub_rn(__fadd_rn(s1, s2), __fmul_rn(2.0f, dot));
                bool hit = (t < tt[k]) && (d2 <= BQ_R2);
                unsigned m = __ballot_sync(FULLW, hit);
                int pos = cnt + __popc(m & below);
                if (hit && pos < BQ_BUF)
                    keyb[pos] = (__float_as_int(p.w) << 17) | a;
                cnt += __popc(m);
            }
        }
    }
    __syncwarp();

    // ---- Staged epilogue ----
    float* ob = sh_out[warp];  // [0..31] mapping, [32..127] coords rank-major
    ob[lane] = 0.0f;
    ob[32 + lane] = 0.0f;
    ob[64 + lane] = 0.0f;
    ob[96 + lane] = 0.0f;
    __syncwarp();

    int cc = cnt < BQ_BUF ? cnt : BQ_BUF;
    if (cc <= 64) {
        // Shfl-based rank: keys for lanes lane / lane+32 in registers;
        // cc-trip uniform loop, no LDS in the loop.
        int ka = (lane < cc) ? keyb[lane] : 0x7fffffff;
        int kb = (32 + lane < cc) ? keyb[32 + lane] : 0x7fffffff;
        int ra = 0, rb = 0;
        for (int j = 0; j < cc; j++) {
            int v = __shfl_sync(FULLW, (j < 32) ? ka : kb, j & 31);
            ra += (v < ka);
            rb += (v < kb);
        }
        if (lane < cc && ra < BQ_K) {
            float4 p = g_cp[ka & 0x1FFFF];
            ob[ra] = (float)(ka >> 17);
            ob[32 + ra * 3 + 0] = p.x;
            ob[32 + ra * 3 + 1] = p.y;
            ob[32 + ra * 3 + 2] = p.z;
        }
        if (32 + lane < cc && rb < BQ_K) {
            float4 p = g_cp[kb & 0x1FFFF];
            ob[rb] = (float)(kb >> 17);
            ob[32 + rb * 3 + 0] = p.x;
            ob[32 + rb * 3 + 1] = p.y;
            ob[32 + rb * 3 + 2] = p.z;
        }
    } else {
        // Rare fallback: full LDS rank loop over all cc keys.
        for (int e0 = lane; e0 < cc; e0 += 32) {
            int key = keyb[e0];
            int rank = 0;
            for (int i = 0; i < cc; i++) rank += (keyb[i] < key);
            if (rank < BQ_K) {
                float4 p = g_cp[key & 0x1FFFF];
                ob[rank] = (float)(key >> 17);
                ob[32 + rank * 3 + 0] = p.x;
                ob[32 + rank * 3 + 1] = p.y;
                ob[32 + rank * 3 + 2] = p.z;
            }
        }
    }
    __syncwarp();

    float* mapping = out + (size_t)q * BQ_K;
    float* coords  = out + (size_t)BQ_N1 * BQ_K + BQ_N1 + (size_t)q * BQ_K * 3;
    mapping[lane] = ob[lane];
    coords[lane] = ob[32 + lane];
    coords[32 + lane] = ob[64 + lane];
    coords[64 + lane] = ob[96 + lane];
    if (lane == 0)
        out[(size_t)BQ_N1 * BQ_K + q] = (float)(cnt < BQ_K ? cnt : BQ_K);
}

extern "C" void kernel_launch(void* const* d_in, const int* in_sizes, int n_in,
                              void* d_out, int out_size) {
    const float* p1 = (const float*)d_in[0];
    const float* p2 = (const float*)d_in[1];
    float* out = (float*)d_out;
    bq_all<<<NBLK, NTHR>>>(p1, p2, out);
}

// round 14
// speedup vs baseline: 1.0171x; 1.0171x over previous
#include <cuda_runtime.h>

// Single fused ball-query kernel, direct-binned 12^3 grid, ONE grid barrier,
// TWO warps per query.
// N1=4096 queries, N2=16384 refs, K=32, r=0.08, points uniform [0,1)^3.
//
// R14 vs R11 (best, 14.56us kernel): 8192 warps (2/query) instead of 4096.
//  - Occupancy cap rises 28 -> ~55 warps/SM (latency hiding ~2x).
//  - Each warp scans alternating rows (r = half, half+2, ...) of the 9-row
//    neighborhood: per-warp serial path ~halves.
//  - Pair merges via the query's shared key buffer (shared-atomic append,
//    the R11-proven pattern), __syncthreads, then 64-lane joint epilogue.
// Geometry: 1024 blocks x 256 threads, launch_bounds(256,7) -> 1036 >= 1024
// co-resident (barrier-safe), 36-reg cap.
// R12/R13's ballot-append + shfl epilogue REVERTED (measured regression:
// ballot re-created a loop-carried serial chain; shfl rank serializes at
// SHFL latency).
//
// Replay-safe: g_tick monotone; parity zeroing re-establishes the counter
// invariant each call. Deterministic: hits ranked by unique original index;
// append order never reaches the output.
//
// Hit predicate bit-identical to verified formula (rel_err 0.0 x12):
//   s = ((x*x + y*y) + z*z)  (mul/add, no fma contraction)
//   dot = fmaf(z1,z2, fmaf(y1,y2, x1*x2))
//   d2  = (s1 + s2) - 2*dot;  hit iff d2 <= r^2

#define BQ_N1 4096
#define BQ_N2 16384
#define BQ_K 32
#define BQ_R2 0.0064f
#define BQ_R2P 0.00641f
#define BQ_G 12
#define BQ_NC (BQ_G * BQ_G * BQ_G)  // 1728
#define BQ_CAP 48
#define BQ_BUF 128
#define NBLK 1024
#define NTHR 256
#define QPB 4                       // queries per block (8 warps / 2)
#define ZPB 2                       // 1024*2 = 2048 >= 1728
#define PPB 16                      // 1024*16 = 16384

__device__ unsigned g_tick;             // entry tickets (monotone)
__device__ unsigned g_arrive;           // barrier arrival tickets (monotone)
__device__ unsigned g_release;          // barrier release generations
__device__ int g_n[2][BQ_NC];           // parity-double-buffered counts
__device__ float4 g_cp[BQ_NC * BQ_CAP]; // x, y, z, idx_bits

__device__ __forceinline__ int cell1(float v) {
    int c = (int)(v * (float)BQ_G);
    return c < 0 ? 0 : (c > BQ_G - 1 ? BQ_G - 1 : c);
}

// Fence-free grid barrier (acq_rel ticket / release-word split).
// 1024 blocks co-resident (launch_bounds(256,7): 7*148 = 1036 >= 1024).
__device__ __forceinline__ void gbar() {
    __syncthreads();
    if (threadIdx.x == 0) {
        unsigned my;
        asm volatile("atom.add.acq_rel.gpu.global.u32 %0, [%1], %2;"
                     : "=r"(my) : "l"(&g_arrive), "r"(1u) : "memory");
        unsigned target = my / NBLK + 1u;
        if (my % NBLK == NBLK - 1u) {
            asm volatile("red.add.release.gpu.global.u32 [%0], %1;"
                         :: "l"(&g_release), "r"(1u) : "memory");
        } else {
            unsigned v;
            do {
                __nanosleep(20);
                asm volatile("ld.acquire.gpu.global.u32 %0, [%1];"
                             : "=r"(v) : "l"(&g_release) : "memory");
            } while (v < target);
        }
    }
    __syncthreads();
}

__global__ __launch_bounds__(NTHR, 7) void bq_all(const float* __restrict__ p1,
                                                  const float* __restrict__ p2,
                                                  float* __restrict__ out) {
    __shared__ int sh_key[QPB][BQ_BUF];     // 2 KB packed hit records
    __shared__ float sh_out[QPB][BQ_K * 4]; // 2 KB staged outputs
    __shared__ int s_wcnt[QPB];
    __shared__ unsigned s_call;

    int tid = threadIdx.x;
    int warp = tid >> 5;          // 0..7
    int lane = tid & 31;
    int qi = warp >> 1;           // query slot in block: 0..3
    int half = warp & 1;          // which half of the rows this warp scans
    int q = blockIdx.x * QPB + qi;
    int pairlane = half * 32 + lane;  // 0..63 within the query's warp pair

    // ---- Entry: non-blocking call-index ticket ----
    if (tid == 0) s_call = atomicAdd(&g_tick, 1u) / NBLK;
    if (tid < QPB) s_wcnt[tid] = 0;
    __syncthreads();
    int par = (int)(s_call & 1u);
    int* cnts = g_n[par];

    // Zero the OTHER parity buffer for the next call (no reader exists).
    if (tid < ZPB) {
        int c = blockIdx.x * ZPB + tid;
        if (c < BQ_NC) g_n[1 - par][c] = 0;
    }

    // ---- Build: 16 points/block into g_n[par]/g_cp ----
    if (tid < PPB) {
        int j = blockIdx.x * PPB + tid;
        float px = p2[3 * j + 0];
        float py = p2[3 * j + 1];
        float pz = p2[3 * j + 2];
        int c = (cell1(pz) * BQ_G + cell1(py)) * BQ_G + cell1(px);
        int slot = atomicAdd(&cnts[c], 1);
        if (slot < BQ_CAP)
            g_cp[c * BQ_CAP + slot] =
                make_float4(px, py, pz, __int_as_float(j));
    }

    // Query-point setup (overlaps build latency).
    float x1 = p1[3 * q + 0];
    float y1 = p1[3 * q + 1];
    float z1 = p1[3 * q + 2];
    float s1 = __fadd_rn(__fadd_rn(__fmul_rn(x1, x1), __fmul_rn(y1, y1)),
                         __fmul_rn(z1, z1));
    int cx = cell1(x1), cy = cell1(y1), cz = cell1(z1);
    int xlo = cx > 0 ? cx - 1 : 0;
    int xhi = cx < BQ_G - 1 ? cx + 1 : BQ_G - 1;
    const float invG = 1.0f / (float)BQ_G;
    float dxl = x1 - (float)cx * invG, dxr = (float)(cx + 1) * invG - x1;
    float dyl = y1 - (float)cy * invG, dyr = (float)(cy + 1) * invG - y1;
    float dzl = z1 - (float)cz * invG, dzr = (float)(cz + 1) * invG - z1;
    float dxl2 = dxl * dxl, dxr2 = dxr * dxr;

    gbar();  // build complete -> query may read

    // ---- Query: this warp scans rows r = half, half+2, ... of the 9 ----
    int* keyb = sh_key[qi];
    int* wcnt = &s_wcnt[qi];

    for (int r = half; r < 9; r += 2) {
        int dzi = r / 3 - 1, dyi = r % 3 - 1;
        int zz = cz + dzi, yy = cy + dyi;
        if (zz < 0 || zz >= BQ_G || yy < 0 || yy >= BQ_G) continue;
        float ddz = (dzi < 0) ? dzl : ((dzi > 0) ? dzr : 0.0f);
        float ddy = (dyi < 0) ? dyl : ((dyi > 0) ? dyr : 0.0f);
        float dyz2 = ddz * ddz + ddy * ddy;
        if (dyz2 > BQ_R2P) continue;                   // row unreachable
        int xl = xlo, xh = xhi;
        if (xl < cx && dxl2 + dyz2 > BQ_R2P) xl = cx;  // left cell out
        if (xh > cx && dxr2 + dyz2 > BQ_R2P) xh = cx;  // right cell out
        int c0 = (zz * BQ_G + yy) * BQ_G + xl;
        int nc = xh - xl + 1;
        int n0 = min(cnts[c0], BQ_CAP);
        int n1 = (nc > 1) ? min(cnts[c0 + 1], BQ_CAP) : 0;
        int n2 = (nc > 2) ? min(cnts[c0 + 2], BQ_CAP) : 0;
        int t01 = n0 + n1;
        int tot = t01 + n2;
        int base0 = c0 * BQ_CAP;
        for (int t = lane; t < tot; t += 32) {
            int a = base0 + (t < n0 ? t
                    : (t < t01 ? BQ_CAP + t - n0 : 2 * BQ_CAP + t - t01));
            float4 p = g_cp[a];
            float s2 = __fadd_rn(
                __fadd_rn(__fmul_rn(p.x, p.x), __fmul_rn(p.y, p.y)),
                __fmul_rn(p.z, p.z));
            float dot = fmaf(z1, p.z, fmaf(y1, p.y, __fmul_rn(x1, p.x)));
            float d2 = __fsub_rn(__fadd_rn(s1, s2), __fmul_rn(2.0f, dot));
            if (d2 <= BQ_R2) {
                int pos = atomicAdd(wcnt, 1);
                if (pos < BQ_BUF)
                    keyb[pos] = (__float_as_int(p.w) << 17) | a;
            }
        }
    }

    __syncthreads();  // both warps of every pair have appended
    int cnt = *wcnt;

    // ---- 64-lane joint epilogue per query ----
    float* ob = sh_out[qi];  // [0..31] mapping, [32..127] coords rank-major
    ob[pairlane] = 0.0f;
    ob[64 + pairlane] = 0.0f;
    __syncthreads();  // zeros visible before rank writes

    int cc = cnt < BQ_BUF ? cnt : BQ_BUF;
    // Rank by packed key (idx-major, idx unique) -> reference's "first K in
    // ascending original index" order, independent of append order.
    for (int e0 = pairlane; e0 < cc; e0 += 64) {
        int key = keyb[e0];
        int rank = 0;
        for (int i = 0; i < cc; i++) rank += (keyb[i] < key);
        if (rank < BQ_K) {
            float4 p = g_cp[key & 0x1FFFF];  // L1-hot reload
            ob[rank] = (float)(key >> 17);
            ob[32 + rank * 3 + 0] = p.x;
            ob[32 + rank * 3 + 1] = p.y;
            ob[32 + rank * 3 + 2] = p.z;
        }
    }
    __syncthreads();  // staged outputs complete

    float* mapping = out + (size_t)q * BQ_K;
    float* coords  = out + (size_t)BQ_N1 * BQ_K + BQ_N1 + (size_t)q * BQ_K * 3;
    if (pairlane < BQ_K) mapping[pairlane] = ob[pairlane];
    coords[pairlane] = ob[32 + pairlane];
    if (pairlane < BQ_K) coords[64 + pairlane] = ob[96 + pairlane];
    if (pairlane == 0)
        out[(size_t)BQ_N1 * BQ_K + q] = (float)(cnt < BQ_K ? cnt : BQ_K);
}

extern "C" void kernel_launch(void* const* d_in, const int* in_sizes, int n_in,
                              void* d_out, int out_size) {
    const float* p1 = (const float*)d_in[0];
    const float* p2 = (const float*)d_in[1];
    float* out = (float*)d_out;
    bq_all<<<NBLK, NTHR>>>(p1, p2, out);
}

// round 16
// speedup vs baseline: 1.1356x; 1.1165x over previous
#include <cuda_runtime.h>

// Ball query as TWO kernels linked by Programmatic Dependent Launch (PDL).
// N1=4096 queries, N2=16384 refs, K=32, r=0.08, points uniform [0,1)^3.
//
// R16: the software grid barrier (and its co-residency cap, spin, and
// chip-wide tail convergence) is replaced by PDL: bq_query is launched with
// programmaticStreamSerializationAllowed=1, runs its build-independent
// prologue concurrently with bq_build, then griddepcontrol.wait (full
// primary completion + memory visibility; primary never calls
// launch_dependents, so no early-trigger race). Query blocks exit
// independently -> no tail barrier.
//
// Query phase is the verified R11 code (3x3 batched rows, shared-atomic
// append, LDS rank epilogue, staged coalesced output).
//
// Replay-safe: per-kernel monotone tickets give both kernels the same call
// index (tickA/64 == tickB/512 per call); generation-parity double-buffered
// counters (g_n[par] built this call, g_n[1-par] zeroed for next; first
// call covered by .bss zeros). Deterministic: hits ranked by unique
// original index.
//
// Hit predicate bit-identical to verified formula (rel_err 0.0 x13):
//   s = ((x*x + y*y) + z*z)  (mul/add, no fma contraction)
//   dot = fmaf(z1,z2, fmaf(y1,y2, x1*x2))
//   d2  = (s1 + s2) - 2*dot;  hit iff d2 <= r^2

#define BQ_N1 4096
#define BQ_N2 16384
#define BQ_K 32
#define BQ_R2 0.0064f
#define BQ_R2P 0.00641f
#define BQ_G 12
#define BQ_NC (BQ_G * BQ_G * BQ_G)  // 1728
#define BQ_CAP 48
#define BQ_BUF 128
#define NBLK_A 64                   // build: 64*256 = 16384 threads
#define NBLK_B 512                  // query: 512*8 warps = 4096
#define NWARP 8
#define FULLW 0xffffffffu

__device__ unsigned g_tickA;            // build-kernel call tickets
__device__ unsigned g_tickB;            // query-kernel call tickets
__device__ int g_n[2][BQ_NC];           // parity-double-buffered counts
__device__ float4 g_cp[BQ_NC * BQ_CAP]; // x, y, z, idx_bits

__device__ __forceinline__ int cell1(float v) {
    int c = (int)(v * (float)BQ_G);
    return c < 0 ? 0 : (c > BQ_G - 1 ? BQ_G - 1 : c);
}

// ---- Primary: zero(next parity) + direct bin ----
__global__ __launch_bounds__(256) void bq_build(const float* __restrict__ p2) {
    __shared__ unsigned s_call;
    int tid = threadIdx.x;
    int gid = blockIdx.x * 256 + tid;   // exactly 16384 threads

    if (tid == 0) s_call = atomicAdd(&g_tickA, 1u) / NBLK_A;
    __syncthreads();
    int par = (int)(s_call & 1u);

    // Zero the OTHER parity buffer for the next call (no reader exists now).
    if (gid < BQ_NC) g_n[1 - par][gid] = 0;

    float px = p2[3 * gid + 0];
    float py = p2[3 * gid + 1];
    float pz = p2[3 * gid + 2];
    int c = (cell1(pz) * BQ_G + cell1(py)) * BQ_G + cell1(px);
    int slot = atomicAdd(&g_n[par][c], 1);
    if (slot < BQ_CAP)
        g_cp[c * BQ_CAP + slot] = make_float4(px, py, pz, __int_as_float(gid));
}

// ---- Secondary (PDL): prologue overlaps bq_build, then wait, then scan ----
__global__ __launch_bounds__(256) void bq_query(const float* __restrict__ p1,
                                                float* __restrict__ out) {
    __shared__ int sh_key[NWARP][BQ_BUF];     // 4 KB packed hit records
    __shared__ float sh_out[NWARP][BQ_K * 4]; // 4 KB staged outputs
    __shared__ int s_wcnt[NWARP];
    __shared__ unsigned s_call;

    int tid = threadIdx.x;
    int warp = tid >> 5;
    int lane = tid & 31;
    int q = blockIdx.x * NWARP + warp;        // 4096 queries, one per warp

    if (tid == 0) s_call = atomicAdd(&g_tickB, 1u) / NBLK_B;
    if (tid < NWARP) s_wcnt[tid] = 0;

    // Build-independent prologue (overlaps the primary kernel).
    float* ob = sh_out[warp];  // [0..31] mapping, [32..127] coords rank-major
    ob[lane] = 0.0f;
    ob[32 + lane] = 0.0f;
    ob[64 + lane] = 0.0f;
    ob[96 + lane] = 0.0f;

    float x1 = p1[3 * q + 0];
    float y1 = p1[3 * q + 1];
    float z1 = p1[3 * q + 2];
    float s1 = __fadd_rn(__fadd_rn(__fmul_rn(x1, x1), __fmul_rn(y1, y1)),
                         __fmul_rn(z1, z1));
    int cx = cell1(x1), cy = cell1(y1), cz = cell1(z1);
    int xlo = cx > 0 ? cx - 1 : 0;
    int xhi = cx < BQ_G - 1 ? cx + 1 : BQ_G - 1;
    const float invG = 1.0f / (float)BQ_G;
    float dxl = x1 - (float)cx * invG, dxr = (float)(cx + 1) * invG - x1;
    float dyl = y1 - (float)cy * invG, dyr = (float)(cy + 1) * invG - y1;
    float dzl = z1 - (float)cz * invG, dzr = (float)(cz + 1) * invG - z1;
    float dxl2 = dxl * dxl, dxr2 = dxr * dxr;

    // Row geometry (depends only on the query point).
    int rowc0[9];
    unsigned char rnc[9];
    #pragma unroll
    for (int r = 0; r < 9; r++) {
        int dzi = r / 3 - 1, dyi = r % 3 - 1;
        int zz = cz + dzi, yy = cy + dyi;
        float ddz = (dzi < 0) ? dzl : ((dzi > 0) ? dzr : 0.0f);
        float ddy = (dyi < 0) ? dyl : ((dyi > 0) ? dyr : 0.0f);
        float dyz2 = ddz * ddz + ddy * ddy;
        bool ok = (zz >= 0) && (zz < BQ_G) && (yy >= 0) && (yy < BQ_G) &&
                  (dyz2 <= BQ_R2P);
        int xl = xlo, xh = xhi;
        if (xl < cx && dxl2 + dyz2 > BQ_R2P) xl = cx;
        if (xh > cx && dxr2 + dyz2 > BQ_R2P) xh = cx;
        rowc0[r] = (zz * BQ_G + yy) * BQ_G + xl;
        rnc[r] = ok ? (unsigned char)(xh - xl + 1) : 0;
    }
    __syncthreads();  // s_call + s_wcnt visible

    int par = (int)(s_call & 1u);
    int* cnts = g_n[par];

    // Wait for the primary grid (build) to complete with memory visibility.
    asm volatile("griddepcontrol.wait;" ::: "memory");

    // ---- Scan (R11-verified): counter wave + 3x3 batched rows ----
    int* keyb = sh_key[warp];
    int* wcnt = &s_wcnt[warp];

    int rbase[9], rpack[9];  // rpack = n0 | n01<<8 | tot<<16
    #pragma unroll
    for (int r = 0; r < 9; r++) {
        int c0 = rowc0[r];
        int nc = rnc[r];
        int n0 = 0, n1 = 0, n2 = 0;
        if (nc > 0) {
            n0 = min(cnts[c0], BQ_CAP);
            if (nc > 1) n1 = min(cnts[c0 + 1], BQ_CAP);
            if (nc > 2) n2 = min(cnts[c0 + 2], BQ_CAP);
        }
        rbase[r] = c0 * BQ_CAP;
        rpack[r] = n0 | ((n0 + n1) << 8) | ((n0 + n1 + n2) << 16);
    }

    #pragma unroll
    for (int grp = 0; grp < 3; grp++) {
        float4 pb[3];
        int ta[3], tt[3];
        #pragma unroll
        for (int k = 0; k < 3; k++) {
            int r = grp * 3 + k;
            int n0 = rpack[r] & 0xff;
            int n01 = (rpack[r] >> 8) & 0xff;
            tt[k] = rpack[r] >> 16;
            int t = lane;
            int a = rbase[r] + (t < n0 ? t
                    : (t < n01 ? BQ_CAP + t - n0 : 2 * BQ_CAP + t - n01));
            ta[k] = a;
            if (t < tt[k]) pb[k] = g_cp[a];
        }
        #pragma unroll
        for (int k = 0; k < 3; k++) {
            int r = grp * 3 + k;
            if (lane < tt[k]) {
                float4 p = pb[k];
                float s2 = __fadd_rn(
                    __fadd_rn(__fmul_rn(p.x, p.x), __fmul_rn(p.y, p.y)),
                    __fmul_rn(p.z, p.z));
                float dot = fmaf(z1, p.z, fmaf(y1, p.y, __fmul_rn(x1, p.x)));
                float d2 = __fsub_rn(__fadd_rn(s1, s2), __fmul_rn(2.0f, dot));
                if (d2 <= BQ_R2) {
                    int pos = atomicAdd(wcnt, 1);
                    if (pos < BQ_BUF)
                        keyb[pos] = (__float_as_int(p.w) << 17) | ta[k];
                }
            }
            // Overflow batches (tot > 32, uncommon).
            int n0 = rpack[r] & 0xff;
            int n01 = (rpack[r] >> 8) & 0xff;
            for (int t = 32 + lane; t < tt[k]; t += 32) {
                int a = rbase[r] + (t < n0 ? t
                        : (t < n01 ? BQ_CAP + t - n0 : 2 * BQ_CAP + t - n01));
                float4 p = g_cp[a];
                float s2 = __fadd_rn(
                    __fadd_rn(__fmul_rn(p.x, p.x), __fmul_rn(p.y, p.y)),
                    __fmul_rn(p.z, p.z));
                float dot = fmaf(z1, p.z, fmaf(y1, p.y, __fmul_rn(x1, p.x)));
                float d2 = __fsub_rn(__fadd_rn(s1, s2), __fmul_rn(2.0f, dot));
                if (d2 <= BQ_R2) {
                    int pos = atomicAdd(wcnt, 1);
                    if (pos < BQ_BUF)
                        keyb[pos] = (__float_as_int(p.w) << 17) | a;
                }
            }
        }
    }
    __syncwarp();
    int cnt = *wcnt;
    __syncwarp();

    // ---- Epilogue: LDS rank into staged buffer, coalesced stores ----
    int cc = cnt < BQ_BUF ? cnt : BQ_BUF;
    for (int e0 = lane; e0 < cc; e0 += 32) {
        int key = keyb[e0];
        int rank = 0;
        for (int i = 0; i < cc; i++) rank += (keyb[i] < key);
        if (rank < BQ_K) {
            float4 p = g_cp[key & 0x1FFFF];  // L1-hot reload
            ob[rank] = (float)(key >> 17);
            ob[32 + rank * 3 + 0] = p.x;
            ob[32 + rank * 3 + 1] = p.y;
            ob[32 + rank * 3 + 2] = p.z;
        }
    }
    __syncwarp();

    float* mapping = out + (size_t)q * BQ_K;
    float* coords  = out + (size_t)BQ_N1 * BQ_K + BQ_N1 + (size_t)q * BQ_K * 3;
    mapping[lane] = ob[lane];
    coords[lane] = ob[32 + lane];
    coords[32 + lane] = ob[64 + lane];
    coords[64 + lane] = ob[96 + lane];
    if (lane == 0)
        out[(size_t)BQ_N1 * BQ_K + q] = (float)(cnt < BQ_K ? cnt : BQ_K);
}

extern "C" void kernel_launch(void* const* d_in, const int* in_sizes, int n_in,
                              void* d_out, int out_size) {
    const float* p1 = (const float*)d_in[0];
    const float* p2 = (const float*)d_in[1];
    float* out = (float*)d_out;

    bq_build<<<NBLK_A, 256>>>(p2);

    cudaLaunchConfig_t cfg = {};
    cfg.gridDim = dim3(NBLK_B, 1, 1);
    cfg.blockDim = dim3(256, 1, 1);
    cfg.dynamicSmemBytes = 0;
    cfg.stream = 0;
    cudaLaunchAttribute attr[1];
    attr[0].id = cudaLaunchAttributeProgrammaticStreamSerialization;
    attr[0].val.programmaticStreamSerializationAllowed = 1;
    cfg.attrs = attr;
    cfg.numAttrs = 1;
    cudaLaunchKernelEx(&cfg, bq_query, p1, out);
}